// round 10
// baseline (speedup 1.0000x reference)
#include <cuda_runtime.h>
#include <cuda_fp16.h>
#include <cstdint>

// ---------------- problem constants ----------------
#define B_    128
#define CIN_  64
#define NF_   16
#define COUT_ 256
#define H_    20
#define W_    20
#define HW_   400
#define K_    1024
#define M_    51200

#define MT      64       // M rows per CTA tile
#define KC      64       // K per chunk = 64 cin of one nf  (chunk kc <-> nf)
#define NCHUNK  16
#define NSTAGE  4
#define NTHREADS 256

// ---------------- smem layout (bytes) ----------------
// mbar  [0, 64)   full[s]=s*8, empty[s]=32+s*8
// A     [1024, 33792)   4 x (64 rows x 128B) fp16
#define OFF_A    1024
#define SMEM_TOTAL 33792

// ---------------- device scratch ----------------
__device__ __half g_xT[B_ * HW_ * CIN_];          // 6.55MB: [b][p][cin] fp16
__device__ uint4  g_combF[NCHUNK * 4 * 16 * 32];  // 512KB: B mma fragments
__device__ uint4  g_tapO4[NF_ * HW_];             // 4 byte-offsets (rows) into xT slab
__device__ uint4  g_tapWh[NF_ * HW_];             // 4 weights as duplicated half2

// ---------------- helpers ----------------
__device__ __forceinline__ uint32_t smem_u32(const void* p) {
    uint32_t a;
    asm("{ .reg .u64 t; cvta.to.shared.u64 t, %1; cvt.u32.u64 %0, t; }" : "=r"(a) : "l"(p));
    return a;
}
__device__ __forceinline__ uint32_t pack_h2(float lo, float hi) {
    uint32_t u;
    asm("cvt.rn.f16x2.f32 %0, %1, %2;" : "=r"(u) : "f"(hi), "f"(lo));
    return u;
}
__device__ __forceinline__ void ldsm_x4(uint32_t& r0, uint32_t& r1, uint32_t& r2, uint32_t& r3,
                                        uint32_t addr) {
    asm volatile("ldmatrix.sync.aligned.m8n8.x4.shared.b16 {%0,%1,%2,%3}, [%4];"
                 : "=r"(r0), "=r"(r1), "=r"(r2), "=r"(r3) : "r"(addr));
}
__device__ __forceinline__ void mma_f16(float c[4], uint32_t a0, uint32_t a1, uint32_t a2,
                                        uint32_t a3, uint32_t b0, uint32_t b1) {
    asm volatile("mma.sync.aligned.m16n8k16.row.col.f32.f16.f16.f32 "
                 "{%0,%1,%2,%3}, {%4,%5,%6,%7}, {%8,%9}, {%0,%1,%2,%3};"
                 : "+f"(c[0]), "+f"(c[1]), "+f"(c[2]), "+f"(c[3])
                 : "r"(a0), "r"(a1), "r"(a2), "r"(a3), "r"(b0), "r"(b1));
}
#define MBARRIER_INIT(addr, cnt) \
    asm volatile("mbarrier.init.shared.b64 [%0], %1;" :: "r"((uint32_t)(addr)), "r"((uint32_t)(cnt)) : "memory")
#define MBARRIER_ARRIVE(addr) \
    asm volatile("mbarrier.arrive.shared.b64 _, [%0];" :: "r"((uint32_t)(addr)) : "memory")
#define MBARRIER_WAIT_PARITY(addr, par) do {                                        \
    uint32_t _m = (uint32_t)(addr); uint32_t _p = (uint32_t)(par); uint32_t _d;     \
    asm volatile("{\n\t.reg .pred p;\n\t"                                           \
        "mbarrier.try_wait.parity.shared.b64 p, [%1], %2;\n\t"                      \
        "selp.b32 %0, 1, 0, p;\n\t}" : "=r"(_d) : "r"(_m), "r"(_p) : "memory");     \
    if (!_d) {                                                                      \
        asm volatile("{\n\t.reg .pred P1;\n\t"                                      \
        "WL_%=:\n\t"                                                                \
        "mbarrier.try_wait.parity.shared.b64 P1, [%0], %1;\n\t"                     \
        "@P1 bra.uni WD_%=;\n\tbra.uni WL_%=;\n\tWD_%=:\n\t}"                       \
        :: "r"(_m), "r"(_p) : "memory");                                            \
    }                                                                               \
} while (0)

// ---------------- prologue: x -> xT[b][p][cin] fp16 ----------------
__global__ void xt_kernel(const float* __restrict__ x) {
    int t = blockIdx.x * blockDim.x + threadIdx.x;
    if (t >= B_ * HW_) return;
    int b = t / HW_;
    int p = t % HW_;
    const float* src = x + (size_t)b * CIN_ * HW_ + p;
    uint32_t row[32];
    #pragma unroll
    for (int c = 0; c < 32; c++)
        row[c] = pack_h2(src[(2 * c) * HW_], src[(2 * c + 1) * HW_]);
    uint4* dst = (uint4*)(g_xT + (size_t)t * CIN_);
    #pragma unroll
    for (int q = 0; q < 8; q++)
        dst[q] = make_uint4(row[q * 4], row[q * 4 + 1], row[q * 4 + 2], row[q * 4 + 3]);
}

// ---------------- prologue: tap tables ----------------
__global__ void tap_kernel(const float* __restrict__ flow) {
    int t = blockIdx.x * blockDim.x + threadIdx.x;
    if (t >= NF_ * HW_) return;
    int nf = t / HW_;
    int p  = t % HW_;
    int i  = p / W_;
    int j  = p % W_;

    float fx = flow[((nf * H_ + i) * W_ + j) * 2 + 0];
    float fy = flow[((nf * H_ + i) * W_ + j) * 2 + 1];
    float ix = (float)i + fx;
    float iy = (float)j + fy;
    float bxf = floorf(ix), byf = floorf(iy);
    float s = ix - bxf, tt = iy - byf;
    int bx = (int)bxf, by = (int)byf;

    // NOTE: w10 intentionally equals w01 (replicates the reference's bug).
    float w00 = (1.f - s) * (1.f - tt);
    float w01 = s * (1.f - tt);
    float w10 = s * (1.f - tt);
    float w11 = s * tt;

    int   rs[4] = {bx, bx + 1, bx, bx + 1};
    int   cs[4] = {by, by, by + 1, by + 1};
    float ws[4] = {w00, w01, w10, w11};

    uint32_t o[4], wh[4];
    #pragma unroll
    for (int k = 0; k < 4; k++) {
        int r = min(max(rs[k], 0), H_);
        int c = min(max(cs[k], 0), W_);
        float w = (r == H_ || c == W_) ? 0.f : ws[k];       // zero-pad tap
        int idx = (r == H_ || c == W_) ? 0 : (r * W_ + c);
        o[k]  = (uint32_t)(idx * 128);
        wh[k] = pack_h2(w, w);                              // duplicated half2
    }
    g_tapO4[nf * HW_ + p] = make_uint4(o[0], o[1], o[2], o[3]);
    g_tapWh[nf * HW_ + p] = make_uint4(wh[0], wh[1], wh[2], wh[3]);
}

// ---------------- prologue: comb -> B mma fragments (k = nf*64 + cin) --------
// Index: ((kc*4 + ks)*16 + jn_g)*32 + lane ; words (x,y,z,w) =
//   x: b_lo for n-slice nb..nb+8, y: b_lo for nb+8..+16, z/w: b_hi (k+=8)
__global__ void comb_prep(const float* __restrict__ comb) {
    int t = blockIdx.x * blockDim.x + threadIdx.x;
    if (t >= NCHUNK * 4 * 16 * 32) return;
    int lane = t & 31;
    int jn_g = (t >> 5) & 15;
    int ks   = (t >> 9) & 3;
    int kc   = t >> 11;                  // = nf
    int nb = jn_g * 16;
    int kb = ks * 16;
    int n0 = nb + (lane >> 2);
    int k0 = kb + (lane & 3) * 2;
    // original comb column for (cin=k_local, nf=kc): cin*NF + nf
    auto F = [&](int n, int kl) -> float { return comb[(size_t)n * K_ + kl * NF_ + kc]; };
    uint4 u;
    u.x = pack_h2(F(n0,     k0),     F(n0,     k0 + 1));
    u.y = pack_h2(F(n0 + 8, k0),     F(n0 + 8, k0 + 1));
    u.z = pack_h2(F(n0,     k0 + 8), F(n0,     k0 + 9));
    u.w = pack_h2(F(n0 + 8, k0 + 8), F(n0 + 8, k0 + 9));
    g_combF[t] = u;
}

// ---------------- fused warp-specialized kernel ----------------
__global__ __launch_bounds__(NTHREADS, 1)
void mma_kernel(const float* __restrict__ bias, float* __restrict__ out) {
    extern __shared__ char smem[];
    const uint32_t sb = smem_u32(smem);
    const int tx   = threadIdx.x;
    const int wid  = tx >> 5;
    const int lane = tx & 31;
    const int m0   = blockIdx.x * MT;

    if (tx == 0) {
        #pragma unroll
        for (int s = 0; s < NSTAGE; s++) {
            MBARRIER_INIT(sb + s * 8, 128);        // full
            MBARRIER_INIT(sb + 32 + s * 8, 128);   // empty
        }
    }
    __syncthreads();

    if (wid >= 4) {
        // ================= PRODUCER (warps 4-7): A only =================
        const int pt = tx - 128;          // 0..127
        const int wp = pt >> 5;           // 0..3
        const int u  = lane >> 4;         // pixel unit 0/1
        const int L  = lane & 15;         // 8-byte cin group

        const char* xrow[8];
        int         pp[8];
        uint32_t    sAoff[8];
        #pragma unroll
        for (int j = 0; j < 8; j++) {
            int ml = wp * 16 + j * 2 + u;
            int m  = m0 + ml;
            int b  = m / HW_;
            int p  = m - b * HW_;
            xrow[j]  = (const char*)g_xT + (size_t)b * (HW_ * CIN_ * 2) + L * 8;
            pp[j]    = p;
            sAoff[j] = (uint32_t)(ml * 128) + (((uint32_t)(L * 8)) ^ ((uint32_t)(ml & 7) << 4));
        }

        #pragma unroll 1
        for (int kc = 0; kc < NCHUNK; kc++) {
            const int s = kc & 3;
            if (kc >= NSTAGE)
                MBARRIER_WAIT_PARITY(sb + 32 + s * 8, ((kc - NSTAGE) >> 2) & 1);

            char* aB = smem + OFF_A + s * 8192;
            const uint4* tO = g_tapO4 + kc * HW_;
            const uint4* tW = g_tapWh + kc * HW_;
            #pragma unroll
            for (int j = 0; j < 8; j++) {
                uint4 o4 = __ldg(tO + pp[j]);
                uint4 w4 = __ldg(tW + pp[j]);
                const char* xb = xrow[j];
                uint2 d0 = *(const uint2*)(xb + o4.x);
                uint2 d1 = *(const uint2*)(xb + o4.y);
                uint2 d2 = *(const uint2*)(xb + o4.z);
                uint2 d3 = *(const uint2*)(xb + o4.w);
                __half2 w0 = *(const __half2*)&w4.x;
                __half2 w1 = *(const __half2*)&w4.y;
                __half2 w2 = *(const __half2*)&w4.z;
                __half2 w3 = *(const __half2*)&w4.w;
                __half2 lo = __hmul2(*(const __half2*)&d0.x, w0);
                lo = __hfma2(*(const __half2*)&d1.x, w1, lo);
                lo = __hfma2(*(const __half2*)&d2.x, w2, lo);
                lo = __hfma2(*(const __half2*)&d3.x, w3, lo);
                __half2 hi = __hmul2(*(const __half2*)&d0.y, w0);
                hi = __hfma2(*(const __half2*)&d1.y, w1, hi);
                hi = __hfma2(*(const __half2*)&d2.y, w2, hi);
                hi = __hfma2(*(const __half2*)&d3.y, w3, hi);
                *(uint2*)(aB + sAoff[j]) =
                    make_uint2(*(const uint32_t*)&lo, *(const uint32_t*)&hi);
            }
            MBARRIER_ARRIVE(sb + s * 8);
        }
    } else {
        // ================= CONSUMER (warps 0-3) =================
        const int w = wid;                // N slice [w*64, w*64+64)
        float acc[4][8][4];
        #pragma unroll
        for (int i = 0; i < 4; i++)
            #pragma unroll
            for (int j = 0; j < 8; j++)
                #pragma unroll
                for (int q = 0; q < 4; q++) acc[i][j][q] = 0.f;

        auto lm_addr = [&](uint32_t base, int rowBase, int kByte) -> uint32_t {
            int r  = rowBase + (lane & 7) + 8 * ((lane >> 3) & 1);
            int cb = kByte + 16 * (lane >> 4);
            return base + r * 128 + (uint32_t)(cb ^ ((r & 7) << 4));
        };

        #pragma unroll 1
        for (int kc = 0; kc < NCHUNK; kc++) {
            const int s = kc & 3;

            // issue all 16 B-fragment LDG.128 before the A-wait (L2-resident)
            uint4 bf[4][4];
            {
                const uint4* base = g_combF + ((size_t)kc * 4 * 16 + w * 4) * 32 + lane;
                #pragma unroll
                for (int ks = 0; ks < 4; ks++)
                    #pragma unroll
                    for (int jn = 0; jn < 4; jn++)
                        bf[ks][jn] = __ldg(base + (ks * 16 + jn) * 32);
            }

            MBARRIER_WAIT_PARITY(sb + s * 8, (kc >> 2) & 1);
            const uint32_t aBuf = sb + OFF_A + s * 8192;

            #pragma unroll
            for (int ks = 0; ks < 4; ks++) {
                #pragma unroll
                for (int wm = 0; wm < 4; wm++) {
                    uint32_t a0, a1, a2, a3;
                    ldsm_x4(a0, a1, a2, a3, lm_addr(aBuf, wm * 16, ks * 32));
                    #pragma unroll
                    for (int jn = 0; jn < 4; jn++) {
                        mma_f16(acc[wm][jn * 2 + 0], a0, a1, a2, a3,
                                bf[ks][jn].x, bf[ks][jn].z);
                        mma_f16(acc[wm][jn * 2 + 1], a0, a1, a2, a3,
                                bf[ks][jn].y, bf[ks][jn].w);
                    }
                }
            }
            MBARRIER_ARRIVE(sb + 32 + s * 8);
        }

        // ---- epilogue ----
        const int r = lane >> 2;
        const int c = lane & 3;
        #pragma unroll
        for (int wm = 0; wm < 4; wm++) {
            int mr0 = m0 + wm * 16 + r;
            int mr1 = mr0 + 8;
            int b0i = mr0 / HW_, p0 = mr0 - b0i * HW_;
            int b1i = mr1 / HW_, p1 = mr1 - b1i * HW_;
            float* o0 = out + (size_t)b0i * COUT_ * HW_ + p0;
            float* o1 = out + (size_t)b1i * COUT_ * HW_ + p1;
            #pragma unroll
            for (int j = 0; j < 8; j++) {
                int n0 = w * 64 + (j >> 1) * 16 + (j & 1) * 8 + 2 * c;
                float bz0 = __ldg(bias + n0), bz1 = __ldg(bias + n0 + 1);
                o0[(size_t)n0 * HW_]       = acc[wm][j][0] + bz0;
                o0[(size_t)(n0 + 1) * HW_] = acc[wm][j][1] + bz1;
                o1[(size_t)n0 * HW_]       = acc[wm][j][2] + bz0;
                o1[(size_t)(n0 + 1) * HW_] = acc[wm][j][3] + bz1;
            }
        }
    }
}

extern "C" void kernel_launch(void* const* d_in, const int* in_sizes, int n_in,
                              void* d_out, int out_size) {
    const float* x    = (const float*)d_in[0];
    const float* flow = (const float*)d_in[1];
    const float* comb = (const float*)d_in[2];
    const float* bias = (const float*)d_in[3];
    float* out = (float*)d_out;

    cudaFuncSetAttribute(mma_kernel,
                         cudaFuncAttributeMaxDynamicSharedMemorySize, SMEM_TOTAL);

    xt_kernel<<<(B_ * HW_ + 127) / 128, 128>>>(x);
    tap_kernel<<<(NF_ * HW_ + 255) / 256, 256>>>(flow);
    comb_prep<<<(NCHUNK * 4 * 16 * 32 + 255) / 256, 256>>>(comb);
    mma_kernel<<<M_ / MT, NTHREADS, SMEM_TOTAL>>>(bias, out);
}

// round 12
// speedup vs baseline: 1.1013x; 1.1013x over previous
#include <cuda_runtime.h>
#include <cuda_fp16.h>
#include <cstdint>

// ---------------- problem constants ----------------
#define B_    128
#define CIN_  64
#define NF_   16
#define COUT_ 256
#define H_    20
#define W_    20
#define HW_   400
#define K_    1024
#define M_    51200

#define MT      64       // M rows per CTA tile
#define KC      64       // K per chunk = 64 cin of one nf  (chunk kc <-> nf)
#define NCHUNK  16
#define NSTAGE  4
#define NTHREADS 256

// ---------------- smem layout (bytes) ----------------
// mbar  [0, 64)    full[s]=s*8, empty[s]=32+s*8
// A     [1024,  33792)   4 x (64 rows x 128B)  fp16
// B     [33792, 164864)  4 x (256 rows x 128B) fp16
#define OFF_A    1024
#define OFF_B    33792
#define SMEM_TOTAL 164864

// ---------------- device scratch ----------------
__device__ __half g_xT[B_ * HW_ * CIN_];          // 6.55MB: [b][p][cin] fp16
__device__ uint4  g_combB[NCHUNK * COUT_ * 8];    // 512KB pre-swizzled fp16 B images
__device__ uint4  g_tapO4[NF_ * HW_];             // 4 byte-offsets (rows) into xT slab
__device__ uint4  g_tapWh[NF_ * HW_];             // 4 weights as duplicated half2

// ---------------- helpers ----------------
__device__ __forceinline__ uint32_t smem_u32(const void* p) {
    uint32_t a;
    asm("{ .reg .u64 t; cvta.to.shared.u64 t, %1; cvt.u32.u64 %0, t; }" : "=r"(a) : "l"(p));
    return a;
}
__device__ __forceinline__ uint32_t pack_h2(float lo, float hi) {
    uint32_t u;
    asm("cvt.rn.f16x2.f32 %0, %1, %2;" : "=r"(u) : "f"(hi), "f"(lo));
    return u;
}
__device__ __forceinline__ void ldsm_x4(uint32_t& r0, uint32_t& r1, uint32_t& r2, uint32_t& r3,
                                        uint32_t addr) {
    asm volatile("ldmatrix.sync.aligned.m8n8.x4.shared.b16 {%0,%1,%2,%3}, [%4];"
                 : "=r"(r0), "=r"(r1), "=r"(r2), "=r"(r3) : "r"(addr));
}
__device__ __forceinline__ void mma_f16(float c[4], uint32_t a0, uint32_t a1, uint32_t a2,
                                        uint32_t a3, uint32_t b0, uint32_t b1) {
    asm volatile("mma.sync.aligned.m16n8k16.row.col.f32.f16.f16.f32 "
                 "{%0,%1,%2,%3}, {%4,%5,%6,%7}, {%8,%9}, {%0,%1,%2,%3};"
                 : "+f"(c[0]), "+f"(c[1]), "+f"(c[2]), "+f"(c[3])
                 : "r"(a0), "r"(a1), "r"(a2), "r"(a3), "r"(b0), "r"(b1));
}
__device__ __forceinline__ void cp16(uint32_t dst, const void* src) {
    asm volatile("cp.async.cg.shared.global [%0], [%1], 16;" :: "r"(dst), "l"(src) : "memory");
}
#define MBARRIER_INIT(addr, cnt) \
    asm volatile("mbarrier.init.shared.b64 [%0], %1;" :: "r"((uint32_t)(addr)), "r"((uint32_t)(cnt)) : "memory")
#define MBARRIER_ARRIVE(addr) \
    asm volatile("mbarrier.arrive.shared.b64 _, [%0];" :: "r"((uint32_t)(addr)) : "memory")
#define MBARRIER_WAIT_PARITY(addr, par) do {                                        \
    uint32_t _m = (uint32_t)(addr); uint32_t _p = (uint32_t)(par); uint32_t _d;     \
    asm volatile("{\n\t.reg .pred p;\n\t"                                           \
        "mbarrier.try_wait.parity.shared.b64 p, [%1], %2;\n\t"                      \
        "selp.b32 %0, 1, 0, p;\n\t}" : "=r"(_d) : "r"(_m), "r"(_p) : "memory");     \
    if (!_d) {                                                                      \
        asm volatile("{\n\t.reg .pred P1;\n\t"                                      \
        "WL_%=:\n\t"                                                                \
        "mbarrier.try_wait.parity.shared.b64 P1, [%0], %1;\n\t"                     \
        "@P1 bra.uni WD_%=;\n\tbra.uni WL_%=;\n\tWD_%=:\n\t}"                       \
        :: "r"(_m), "r"(_p) : "memory");                                            \
    }                                                                               \
} while (0)

// ---------------- prologue: x -> xT[b][p][cin] fp16 ----------------
__global__ void xt_kernel(const float* __restrict__ x) {
    int t = blockIdx.x * blockDim.x + threadIdx.x;
    if (t >= B_ * HW_) return;
    int b = t / HW_;
    int p = t % HW_;
    const float* src = x + (size_t)b * CIN_ * HW_ + p;
    uint32_t row[32];
    #pragma unroll
    for (int c = 0; c < 32; c++)
        row[c] = pack_h2(src[(2 * c) * HW_], src[(2 * c + 1) * HW_]);
    uint4* dst = (uint4*)(g_xT + (size_t)t * CIN_);
    #pragma unroll
    for (int q = 0; q < 8; q++)
        dst[q] = make_uint4(row[q * 4], row[q * 4 + 1], row[q * 4 + 2], row[q * 4 + 3]);
}

// ---------------- prologue: tap tables ----------------
__global__ void tap_kernel(const float* __restrict__ flow) {
    int t = blockIdx.x * blockDim.x + threadIdx.x;
    if (t >= NF_ * HW_) return;
    int nf = t / HW_;
    int p  = t % HW_;
    int i  = p / W_;
    int j  = p % W_;

    float fx = flow[((nf * H_ + i) * W_ + j) * 2 + 0];
    float fy = flow[((nf * H_ + i) * W_ + j) * 2 + 1];
    float ix = (float)i + fx;
    float iy = (float)j + fy;
    float bxf = floorf(ix), byf = floorf(iy);
    float s = ix - bxf, tt = iy - byf;
    int bx = (int)bxf, by = (int)byf;

    // NOTE: w10 intentionally equals w01 (replicates the reference's bug).
    float w00 = (1.f - s) * (1.f - tt);
    float w01 = s * (1.f - tt);
    float w10 = s * (1.f - tt);
    float w11 = s * tt;

    int   rs[4] = {bx, bx + 1, bx, bx + 1};
    int   cs[4] = {by, by, by + 1, by + 1};
    float ws[4] = {w00, w01, w10, w11};

    uint32_t o[4], wh[4];
    #pragma unroll
    for (int k = 0; k < 4; k++) {
        int r = min(max(rs[k], 0), H_);
        int c = min(max(cs[k], 0), W_);
        float w = (r == H_ || c == W_) ? 0.f : ws[k];       // zero-pad tap
        int idx = (r == H_ || c == W_) ? 0 : (r * W_ + c);
        o[k]  = (uint32_t)(idx * 128);
        wh[k] = pack_h2(w, w);                              // duplicated half2
    }
    g_tapO4[nf * HW_ + p] = make_uint4(o[0], o[1], o[2], o[3]);
    g_tapWh[nf * HW_ + p] = make_uint4(wh[0], wh[1], wh[2], wh[3]);
}

// ---------------- prologue: comb -> fp16 chunk images, k = nf*64 + cin -------
__global__ void comb_prep(const float* __restrict__ comb) {
    int t = blockIdx.x * blockDim.x + threadIdx.x;
    if (t >= NCHUNK * COUT_) return;
    int kc = t >> 8;                 // = nf
    int o  = t & 255;
    const float* src = comb + (size_t)o * K_ + kc;   // stride 16 floats over cin
    #pragma unroll
    for (int g = 0; g < 8; g++) {
        uint4 u;
        u.x = pack_h2(src[(g * 8 + 0) * NF_], src[(g * 8 + 1) * NF_]);
        u.y = pack_h2(src[(g * 8 + 2) * NF_], src[(g * 8 + 3) * NF_]);
        u.z = pack_h2(src[(g * 8 + 4) * NF_], src[(g * 8 + 5) * NF_]);
        u.w = pack_h2(src[(g * 8 + 6) * NF_], src[(g * 8 + 7) * NF_]);
        g_combB[(kc * COUT_ + o) * 8 + (g ^ (o & 7))] = u;
    }
}

// ---------------- fused warp-specialized kernel ----------------
__global__ __launch_bounds__(NTHREADS, 1)
void mma_kernel(const float* __restrict__ bias, float* __restrict__ out) {
    extern __shared__ char smem[];
    const uint32_t sb = smem_u32(smem);
    const int tx   = threadIdx.x;
    const int wid  = tx >> 5;
    const int lane = tx & 31;
    const int m0   = blockIdx.x * MT;

    if (tx == 0) {
        #pragma unroll
        for (int s = 0; s < NSTAGE; s++) {
            MBARRIER_INIT(sb + s * 8, 128);       // full
            MBARRIER_INIT(sb + 32 + s * 8, 128);  // empty
        }
    }
    __syncthreads();

    if (wid >= 4) {
        // ================= PRODUCER (warps 4-7) =================
        const int pt = tx - 128;          // 0..127
        const int wp = pt >> 5;           // 0..3
        const int u  = lane >> 4;         // pixel unit 0/1
        const int L  = lane & 15;         // 8-byte cin group

        const char* xrow[8];
        int         pp[8];
        uint32_t    sAoff[8];
        #pragma unroll
        for (int j = 0; j < 8; j++) {
            int ml = wp * 16 + j * 2 + u;
            int m  = m0 + ml;
            int b  = m / HW_;
            int p  = m - b * HW_;
            xrow[j]  = (const char*)g_xT + (size_t)b * (HW_ * CIN_ * 2) + L * 8;
            pp[j]    = p;
            sAoff[j] = (uint32_t)(ml * 128) + (((uint32_t)(L * 8)) ^ ((uint32_t)(ml & 7) << 4));
        }

        #pragma unroll 1
        for (int kc = 0; kc < NCHUNK; kc++) {
            const int s = kc & 3;
            if (kc >= NSTAGE)
                MBARRIER_WAIT_PARITY(sb + 32 + s * 8, ((kc - NSTAGE) >> 2) & 1);

            // ---- B: cp.async pre-swizzled image (32KB over 128 threads) ----
            {
                const char* bsrc = (const char*)g_combB + (size_t)kc * 32768;
                uint32_t bdst = sb + OFF_B + s * 32768;
                #pragma unroll
                for (int i = 0; i < 16; i++)
                    cp16(bdst + (pt + i * 128) * 16, bsrc + (size_t)(pt + i * 128) * 16);
                asm volatile("cp.async.commit_group;" ::: "memory");
            }

            // ---- A: coalesced gathers, HFMA2 tap math ----
            {
                char* aB = smem + OFF_A + s * 8192;
                const uint4* tO = g_tapO4 + kc * HW_;
                const uint4* tW = g_tapWh + kc * HW_;
                #pragma unroll
                for (int j = 0; j < 8; j++) {
                    uint4 o4 = __ldg(tO + pp[j]);
                    uint4 w4 = __ldg(tW + pp[j]);
                    const char* xb = xrow[j];
                    uint2 d0 = *(const uint2*)(xb + o4.x);
                    uint2 d1 = *(const uint2*)(xb + o4.y);
                    uint2 d2 = *(const uint2*)(xb + o4.z);
                    uint2 d3 = *(const uint2*)(xb + o4.w);
                    __half2 w0 = *(const __half2*)&w4.x;
                    __half2 w1 = *(const __half2*)&w4.y;
                    __half2 w2 = *(const __half2*)&w4.z;
                    __half2 w3 = *(const __half2*)&w4.w;
                    __half2 lo = __hmul2(*(const __half2*)&d0.x, w0);
                    lo = __hfma2(*(const __half2*)&d1.x, w1, lo);
                    lo = __hfma2(*(const __half2*)&d2.x, w2, lo);
                    lo = __hfma2(*(const __half2*)&d3.x, w3, lo);
                    __half2 hi = __hmul2(*(const __half2*)&d0.y, w0);
                    hi = __hfma2(*(const __half2*)&d1.y, w1, hi);
                    hi = __hfma2(*(const __half2*)&d2.y, w2, hi);
                    hi = __hfma2(*(const __half2*)&d3.y, w3, hi);
                    *(uint2*)(aB + sAoff[j]) =
                        make_uint2(*(const uint32_t*)&lo, *(const uint32_t*)&hi);
                }
            }

            asm volatile("cp.async.wait_group 0;" ::: "memory");
            MBARRIER_ARRIVE(sb + s * 8);
        }
    } else {
        // ================= CONSUMER (warps 0-3) =================
        const int w = wid;                // N slice [w*64, w*64+64)
        float acc[4][8][4];
        #pragma unroll
        for (int i = 0; i < 4; i++)
            #pragma unroll
            for (int j = 0; j < 8; j++)
                #pragma unroll
                for (int q = 0; q < 4; q++) acc[i][j][q] = 0.f;

        auto lm_addr = [&](uint32_t base, int rowBase, int kByte) -> uint32_t {
            int r  = rowBase + (lane & 7) + 8 * ((lane >> 3) & 1);
            int cb = kByte + 16 * (lane >> 4);
            return base + r * 128 + (uint32_t)(cb ^ ((r & 7) << 4));
        };

        #pragma unroll 1
        for (int kc = 0; kc < NCHUNK; kc++) {
            const int s = kc & 3;
            MBARRIER_WAIT_PARITY(sb + s * 8, (kc >> 2) & 1);
            const uint32_t aBuf = sb + OFF_A + s * 8192;
            const uint32_t bBuf = sb + OFF_B + s * 32768;

            #pragma unroll
            for (int ks = 0; ks < 4; ks++) {
                const int kB = ks * 32;
                uint32_t bb[4][4];
                #pragma unroll
                for (int jn = 0; jn < 4; jn++)
                    ldsm_x4(bb[jn][0], bb[jn][1], bb[jn][2], bb[jn][3],
                            lm_addr(bBuf, w * 64 + jn * 16, kB));
                #pragma unroll
                for (int wm = 0; wm < 4; wm++) {
                    uint32_t a0, a1, a2, a3;
                    ldsm_x4(a0, a1, a2, a3, lm_addr(aBuf, wm * 16, kB));
                    #pragma unroll
                    for (int jn = 0; jn < 4; jn++) {
                        mma_f16(acc[wm][jn * 2 + 0], a0, a1, a2, a3, bb[jn][0], bb[jn][2]);
                        mma_f16(acc[wm][jn * 2 + 1], a0, a1, a2, a3, bb[jn][1], bb[jn][3]);
                    }
                }
            }
            MBARRIER_ARRIVE(sb + 32 + s * 8);
        }

        // ---- epilogue ----
        const int r = lane >> 2;
        const int c = lane & 3;
        #pragma unroll
        for (int wm = 0; wm < 4; wm++) {
            int mr0 = m0 + wm * 16 + r;
            int mr1 = mr0 + 8;
            int b0i = mr0 / HW_, p0 = mr0 - b0i * HW_;
            int b1i = mr1 / HW_, p1 = mr1 - b1i * HW_;
            float* o0 = out + (size_t)b0i * COUT_ * HW_ + p0;
            float* o1 = out + (size_t)b1i * COUT_ * HW_ + p1;
            #pragma unroll
            for (int j = 0; j < 8; j++) {
                int n0 = w * 64 + (j >> 1) * 16 + (j & 1) * 8 + 2 * c;
                float bz0 = __ldg(bias + n0), bz1 = __ldg(bias + n0 + 1);
                o0[(size_t)n0 * HW_]       = acc[wm][j][0] + bz0;
                o0[(size_t)(n0 + 1) * HW_] = acc[wm][j][1] + bz1;
                o1[(size_t)n0 * HW_]       = acc[wm][j][2] + bz0;
                o1[(size_t)(n0 + 1) * HW_] = acc[wm][j][3] + bz1;
            }
        }
    }
}

extern "C" void kernel_launch(void* const* d_in, const int* in_sizes, int n_in,
                              void* d_out, int out_size) {
    const float* x    = (const float*)d_in[0];
    const float* flow = (const float*)d_in[1];
    const float* comb = (const float*)d_in[2];
    const float* bias = (const float*)d_in[3];
    float* out = (float*)d_out;

    cudaFuncSetAttribute(mma_kernel,
                         cudaFuncAttributeMaxDynamicSharedMemorySize, SMEM_TOTAL);

    xt_kernel<<<(B_ * HW_ + 127) / 128, 128>>>(x);
    tap_kernel<<<(NF_ * HW_ + 255) / 256, 256>>>(flow);
    comb_prep<<<(NCHUNK * COUT_ + 255) / 256, 256>>>(comb);
    mma_kernel<<<M_ / MT, NTHREADS, SMEM_TOTAL>>>(bias, out);
}

// round 13
// speedup vs baseline: 1.1594x; 1.0527x over previous
#include <cuda_runtime.h>
#include <cuda_fp16.h>
#include <cstdint>

// ---------------- problem constants ----------------
#define B_    128
#define CIN_  64
#define NF_   16
#define COUT_ 256
#define H_    20
#define W_    20
#define HW_   400
#define K_    1024
#define M_    51200

#define MT      64       // M rows per CTA tile
#define KC      64       // K per chunk = 64 cin of one nf  (chunk kc <-> nf)
#define NCHUNK  16
#define NSTAGE  4
#define NTHREADS 512     // 8 consumer + 8 producer warps

// ---------------- smem layout (bytes) ----------------
// mbar  [0, 64)    full[s]=s*8, empty[s]=32+s*8
// A     [1024,  33792)   4 x (64 rows x 128B)  fp16
// B     [33792, 164864)  4 x (256 rows x 128B) fp16
#define OFF_A    1024
#define OFF_B    33792
#define SMEM_TOTAL 164864

// ---------------- device scratch ----------------
__device__ __half g_xT[B_ * HW_ * CIN_];          // 6.55MB: [b][p][cin] fp16
__device__ uint4  g_combB[NCHUNK * COUT_ * 8];    // 512KB pre-swizzled fp16 B images
__device__ uint4  g_tapO4[NF_ * HW_];             // 4 byte-offsets (rows) into xT slab
__device__ uint4  g_tapWh[NF_ * HW_];             // 4 weights as duplicated half2

// ---------------- helpers ----------------
__device__ __forceinline__ uint32_t smem_u32(const void* p) {
    uint32_t a;
    asm("{ .reg .u64 t; cvta.to.shared.u64 t, %1; cvt.u32.u64 %0, t; }" : "=r"(a) : "l"(p));
    return a;
}
__device__ __forceinline__ uint32_t pack_h2(float lo, float hi) {
    uint32_t u;
    asm("cvt.rn.f16x2.f32 %0, %1, %2;" : "=r"(u) : "f"(hi), "f"(lo));
    return u;
}
__device__ __forceinline__ void ldsm_x4(uint32_t& r0, uint32_t& r1, uint32_t& r2, uint32_t& r3,
                                        uint32_t addr) {
    asm volatile("ldmatrix.sync.aligned.m8n8.x4.shared.b16 {%0,%1,%2,%3}, [%4];"
                 : "=r"(r0), "=r"(r1), "=r"(r2), "=r"(r3) : "r"(addr));
}
__device__ __forceinline__ void mma_f16(float c[4], uint32_t a0, uint32_t a1, uint32_t a2,
                                        uint32_t a3, uint32_t b0, uint32_t b1) {
    asm volatile("mma.sync.aligned.m16n8k16.row.col.f32.f16.f16.f32 "
                 "{%0,%1,%2,%3}, {%4,%5,%6,%7}, {%8,%9}, {%0,%1,%2,%3};"
                 : "+f"(c[0]), "+f"(c[1]), "+f"(c[2]), "+f"(c[3])
                 : "r"(a0), "r"(a1), "r"(a2), "r"(a3), "r"(b0), "r"(b1));
}
__device__ __forceinline__ void cp16(uint32_t dst, const void* src) {
    asm volatile("cp.async.cg.shared.global [%0], [%1], 16;" :: "r"(dst), "l"(src) : "memory");
}
#define MBARRIER_INIT(addr, cnt) \
    asm volatile("mbarrier.init.shared.b64 [%0], %1;" :: "r"((uint32_t)(addr)), "r"((uint32_t)(cnt)) : "memory")
#define MBARRIER_ARRIVE(addr) \
    asm volatile("mbarrier.arrive.shared.b64 _, [%0];" :: "r"((uint32_t)(addr)) : "memory")
#define MBARRIER_WAIT_PARITY(addr, par) do {                                        \
    uint32_t _m = (uint32_t)(addr); uint32_t _p = (uint32_t)(par); uint32_t _d;     \
    asm volatile("{\n\t.reg .pred p;\n\t"                                           \
        "mbarrier.try_wait.parity.shared.b64 p, [%1], %2;\n\t"                      \
        "selp.b32 %0, 1, 0, p;\n\t}" : "=r"(_d) : "r"(_m), "r"(_p) : "memory");     \
    if (!_d) {                                                                      \
        asm volatile("{\n\t.reg .pred P1;\n\t"                                      \
        "WL_%=:\n\t"                                                                \
        "mbarrier.try_wait.parity.shared.b64 P1, [%0], %1;\n\t"                     \
        "@P1 bra.uni WD_%=;\n\tbra.uni WL_%=;\n\tWD_%=:\n\t}"                       \
        :: "r"(_m), "r"(_p) : "memory");                                            \
    }                                                                               \
} while (0)

// ---------------- prologue: x -> xT[b][p][cin] fp16 ----------------
__global__ void xt_kernel(const float* __restrict__ x) {
    int t = blockIdx.x * blockDim.x + threadIdx.x;
    if (t >= B_ * HW_) return;
    int b = t / HW_;
    int p = t % HW_;
    const float* src = x + (size_t)b * CIN_ * HW_ + p;
    uint32_t row[32];
    #pragma unroll
    for (int c = 0; c < 32; c++)
        row[c] = pack_h2(src[(2 * c) * HW_], src[(2 * c + 1) * HW_]);
    uint4* dst = (uint4*)(g_xT + (size_t)t * CIN_);
    #pragma unroll
    for (int q = 0; q < 8; q++)
        dst[q] = make_uint4(row[q * 4], row[q * 4 + 1], row[q * 4 + 2], row[q * 4 + 3]);
}

// ---------------- prologue: tap tables ----------------
__global__ void tap_kernel(const float* __restrict__ flow) {
    int t = blockIdx.x * blockDim.x + threadIdx.x;
    if (t >= NF_ * HW_) return;
    int nf = t / HW_;
    int p  = t % HW_;
    int i  = p / W_;
    int j  = p % W_;

    float fx = flow[((nf * H_ + i) * W_ + j) * 2 + 0];
    float fy = flow[((nf * H_ + i) * W_ + j) * 2 + 1];
    float ix = (float)i + fx;
    float iy = (float)j + fy;
    float bxf = floorf(ix), byf = floorf(iy);
    float s = ix - bxf, tt = iy - byf;
    int bx = (int)bxf, by = (int)byf;

    // NOTE: w10 intentionally equals w01 (replicates the reference's bug).
    float w00 = (1.f - s) * (1.f - tt);
    float w01 = s * (1.f - tt);
    float w10 = s * (1.f - tt);
    float w11 = s * tt;

    int   rs[4] = {bx, bx + 1, bx, bx + 1};
    int   cs[4] = {by, by, by + 1, by + 1};
    float ws[4] = {w00, w01, w10, w11};

    uint32_t o[4], wh[4];
    #pragma unroll
    for (int k = 0; k < 4; k++) {
        int r = min(max(rs[k], 0), H_);
        int c = min(max(cs[k], 0), W_);
        float w = (r == H_ || c == W_) ? 0.f : ws[k];       // zero-pad tap
        int idx = (r == H_ || c == W_) ? 0 : (r * W_ + c);
        o[k]  = (uint32_t)(idx * 128);
        wh[k] = pack_h2(w, w);                              // duplicated half2
    }
    g_tapO4[nf * HW_ + p] = make_uint4(o[0], o[1], o[2], o[3]);
    g_tapWh[nf * HW_ + p] = make_uint4(wh[0], wh[1], wh[2], wh[3]);
}

// ---------------- prologue: comb -> fp16 chunk images, k = nf*64 + cin -------
__global__ void comb_prep(const float* __restrict__ comb) {
    int t = blockIdx.x * blockDim.x + threadIdx.x;
    if (t >= NCHUNK * COUT_) return;
    int kc = t >> 8;                 // = nf
    int o  = t & 255;
    const float* src = comb + (size_t)o * K_ + kc;   // stride 16 floats over cin
    #pragma unroll
    for (int g = 0; g < 8; g++) {
        uint4 u;
        u.x = pack_h2(src[(g * 8 + 0) * NF_], src[(g * 8 + 1) * NF_]);
        u.y = pack_h2(src[(g * 8 + 2) * NF_], src[(g * 8 + 3) * NF_]);
        u.z = pack_h2(src[(g * 8 + 4) * NF_], src[(g * 8 + 5) * NF_]);
        u.w = pack_h2(src[(g * 8 + 6) * NF_], src[(g * 8 + 7) * NF_]);
        g_combB[(kc * COUT_ + o) * 8 + (g ^ (o & 7))] = u;
    }
}

// ---------------- fused warp-specialized kernel ----------------
__global__ __launch_bounds__(NTHREADS, 1)
void mma_kernel(const float* __restrict__ bias, float* __restrict__ out) {
    extern __shared__ char smem[];
    const uint32_t sb = smem_u32(smem);
    const int tx   = threadIdx.x;
    const int wid  = tx >> 5;
    const int lane = tx & 31;
    const int m0   = blockIdx.x * MT;

    if (tx == 0) {
        #pragma unroll
        for (int s = 0; s < NSTAGE; s++) {
            MBARRIER_INIT(sb + s * 8, 256);       // full:  256 producer threads
            MBARRIER_INIT(sb + 32 + s * 8, 256);  // empty: 256 consumer threads
        }
    }
    __syncthreads();

    if (wid >= 8) {
        // ================= PRODUCER (warps 8-15) =================
        const int pt = tx - 256;          // 0..255
        const int L  = pt & 15;           // 8-byte cin group
        const int rb = pt >> 4;           // row base 0..15 (rows rb + 16*j)

        const char* xrow[4];
        int         pp[4];
        uint32_t    sAoff[4];
        #pragma unroll
        for (int j = 0; j < 4; j++) {
            int ml = rb + 16 * j;
            int m  = m0 + ml;
            int b  = m / HW_;
            int p  = m - b * HW_;
            xrow[j]  = (const char*)g_xT + (size_t)b * (HW_ * CIN_ * 2) + L * 8;
            pp[j]    = p;
            sAoff[j] = (uint32_t)(ml * 128) + (((uint32_t)(L * 8)) ^ ((uint32_t)(ml & 7) << 4));
        }

        #pragma unroll 1
        for (int kc = 0; kc < NCHUNK; kc++) {
            const int s = kc & 3;
            if (kc >= NSTAGE)
                MBARRIER_WAIT_PARITY(sb + 32 + s * 8, ((kc - NSTAGE) >> 2) & 1);

            // ---- B: cp.async pre-swizzled image (32KB over 256 threads) ----
            {
                const char* bsrc = (const char*)g_combB + (size_t)kc * 32768;
                uint32_t bdst = sb + OFF_B + s * 32768;
                #pragma unroll
                for (int i = 0; i < 8; i++)
                    cp16(bdst + (pt + i * 256) * 16, bsrc + (size_t)(pt + i * 256) * 16);
                asm volatile("cp.async.commit_group;" ::: "memory");
            }

            // ---- A: coalesced gathers, HFMA2 tap math ----
            {
                char* aB = smem + OFF_A + s * 8192;
                const uint4* tO = g_tapO4 + kc * HW_;
                const uint4* tW = g_tapWh + kc * HW_;
                #pragma unroll
                for (int j = 0; j < 4; j++) {
                    uint4 o4 = __ldg(tO + pp[j]);
                    uint4 w4 = __ldg(tW + pp[j]);
                    const char* xb = xrow[j];
                    uint2 d0 = *(const uint2*)(xb + o4.x);
                    uint2 d1 = *(const uint2*)(xb + o4.y);
                    uint2 d2 = *(const uint2*)(xb + o4.z);
                    uint2 d3 = *(const uint2*)(xb + o4.w);
                    __half2 w0 = *(const __half2*)&w4.x;
                    __half2 w1 = *(const __half2*)&w4.y;
                    __half2 w2 = *(const __half2*)&w4.z;
                    __half2 w3 = *(const __half2*)&w4.w;
                    __half2 lo = __hmul2(*(const __half2*)&d0.x, w0);
                    lo = __hfma2(*(const __half2*)&d1.x, w1, lo);
                    lo = __hfma2(*(const __half2*)&d2.x, w2, lo);
                    lo = __hfma2(*(const __half2*)&d3.x, w3, lo);
                    __half2 hi = __hmul2(*(const __half2*)&d0.y, w0);
                    hi = __hfma2(*(const __half2*)&d1.y, w1, hi);
                    hi = __hfma2(*(const __half2*)&d2.y, w2, hi);
                    hi = __hfma2(*(const __half2*)&d3.y, w3, hi);
                    *(uint2*)(aB + sAoff[j]) =
                        make_uint2(*(const uint32_t*)&lo, *(const uint32_t*)&hi);
                }
            }

            asm volatile("cp.async.wait_group 0;" ::: "memory");
            MBARRIER_ARRIVE(sb + s * 8);
        }
    } else {
        // ================= CONSUMER (warps 0-7) =================
        const int warpM = wid & 1;        // M half: rows [warpM*32, +32)
        const int warpN = wid >> 1;       // N slice [warpN*64, +64)
        float acc[2][8][4];
        #pragma unroll
        for (int i = 0; i < 2; i++)
            #pragma unroll
            for (int j = 0; j < 8; j++)
                #pragma unroll
                for (int q = 0; q < 4; q++) acc[i][j][q] = 0.f;

        auto lm_addr = [&](uint32_t base, int rowBase, int kByte) -> uint32_t {
            int r  = rowBase + (lane & 7) + 8 * ((lane >> 3) & 1);
            int cb = kByte + 16 * (lane >> 4);
            return base + r * 128 + (uint32_t)(cb ^ ((r & 7) << 4));
        };

        #pragma unroll 1
        for (int kc = 0; kc < NCHUNK; kc++) {
            const int s = kc & 3;
            MBARRIER_WAIT_PARITY(sb + s * 8, (kc >> 2) & 1);
            const uint32_t aBuf = sb + OFF_A + s * 8192;
            const uint32_t bBuf = sb + OFF_B + s * 32768;

            #pragma unroll
            for (int ks = 0; ks < 4; ks++) {
                const int kB = ks * 32;
                uint32_t bb[4][4];
                #pragma unroll
                for (int jn = 0; jn < 4; jn++)
                    ldsm_x4(bb[jn][0], bb[jn][1], bb[jn][2], bb[jn][3],
                            lm_addr(bBuf, warpN * 64 + jn * 16, kB));
                #pragma unroll
                for (int wm = 0; wm < 2; wm++) {
                    uint32_t a0, a1, a2, a3;
                    ldsm_x4(a0, a1, a2, a3, lm_addr(aBuf, warpM * 32 + wm * 16, kB));
                    #pragma unroll
                    for (int jn = 0; jn < 4; jn++) {
                        mma_f16(acc[wm][jn * 2 + 0], a0, a1, a2, a3, bb[jn][0], bb[jn][2]);
                        mma_f16(acc[wm][jn * 2 + 1], a0, a1, a2, a3, bb[jn][1], bb[jn][3]);
                    }
                }
            }
            MBARRIER_ARRIVE(sb + 32 + s * 8);
        }

        // ---- epilogue ----
        const int r = lane >> 2;
        const int c = lane & 3;
        #pragma unroll
        for (int wm = 0; wm < 2; wm++) {
            int mr0 = m0 + warpM * 32 + wm * 16 + r;
            int mr1 = mr0 + 8;
            int b0i = mr0 / HW_, p0 = mr0 - b0i * HW_;
            int b1i = mr1 / HW_, p1 = mr1 - b1i * HW_;
            float* o0 = out + (size_t)b0i * COUT_ * HW_ + p0;
            float* o1 = out + (size_t)b1i * COUT_ * HW_ + p1;
            #pragma unroll
            for (int j = 0; j < 8; j++) {
                int n0 = warpN * 64 + (j >> 1) * 16 + (j & 1) * 8 + 2 * c;
                float bz0 = __ldg(bias + n0), bz1 = __ldg(bias + n0 + 1);
                o0[(size_t)n0 * HW_]       = acc[wm][j][0] + bz0;
                o0[(size_t)(n0 + 1) * HW_] = acc[wm][j][1] + bz1;
                o1[(size_t)n0 * HW_]       = acc[wm][j][2] + bz0;
                o1[(size_t)(n0 + 1) * HW_] = acc[wm][j][3] + bz1;
            }
        }
    }
}

extern "C" void kernel_launch(void* const* d_in, const int* in_sizes, int n_in,
                              void* d_out, int out_size) {
    const float* x    = (const float*)d_in[0];
    const float* flow = (const float*)d_in[1];
    const float* comb = (const float*)d_in[2];
    const float* bias = (const float*)d_in[3];
    float* out = (float*)d_out;

    cudaFuncSetAttribute(mma_kernel,
                         cudaFuncAttributeMaxDynamicSharedMemorySize, SMEM_TOTAL);

    xt_kernel<<<(B_ * HW_ + 127) / 128, 128>>>(x);
    tap_kernel<<<(NF_ * HW_ + 255) / 256, 256>>>(flow);
    comb_prep<<<(NCHUNK * COUT_ + 255) / 256, 256>>>(comb);
    mma_kernel<<<M_ / MT, NTHREADS, SMEM_TOTAL>>>(bias, out);
}

// round 15
// speedup vs baseline: 1.2328x; 1.0633x over previous
#include <cuda_runtime.h>
#include <cuda_fp16.h>
#include <cstdint>

// ---------------- problem constants ----------------
#define B_    128
#define CIN_  64
#define NF_   16
#define COUT_ 256
#define H_    20
#define W_    20
#define HW_   400
#define K_    1024
#define M_    51200

#define MT      64       // M rows per CTA tile
#define KC      64       // K per chunk = 64 cin of one nf  (chunk kc <-> nf)
#define NCHUNK  16
#define NSTAGE  4
#define NTHREADS 512     // 8 consumer + 8 producer warps

// ---------------- smem layout (bytes) ----------------
// mbar  [0, 64)    full[s]=s*8, empty[s]=32+s*8
// A     [1024, 33792)   4 x (64 rows x 128B) fp16
#define OFF_A    1024
#define SMEM_TOTAL 33792

// ---------------- device scratch ----------------
__device__ __half g_xT[B_ * HW_ * CIN_];          // 6.55MB: [b][p][cin] fp16
__device__ uint4  g_combF[NCHUNK * 4 * 16 * 32];  // 512KB: B mma fragments
__device__ uint4  g_tapO4[NF_ * HW_];             // 4 byte-offsets (rows) into xT slab
__device__ uint4  g_tapWh[NF_ * HW_];             // 4 weights as duplicated half2

// ---------------- helpers ----------------
__device__ __forceinline__ uint32_t smem_u32(const void* p) {
    uint32_t a;
    asm("{ .reg .u64 t; cvta.to.shared.u64 t, %1; cvt.u32.u64 %0, t; }" : "=r"(a) : "l"(p));
    return a;
}
__device__ __forceinline__ uint32_t pack_h2(float lo, float hi) {
    uint32_t u;
    asm("cvt.rn.f16x2.f32 %0, %1, %2;" : "=r"(u) : "f"(hi), "f"(lo));
    return u;
}
__device__ __forceinline__ void ldsm_x4(uint32_t& r0, uint32_t& r1, uint32_t& r2, uint32_t& r3,
                                        uint32_t addr) {
    asm volatile("ldmatrix.sync.aligned.m8n8.x4.shared.b16 {%0,%1,%2,%3}, [%4];"
                 : "=r"(r0), "=r"(r1), "=r"(r2), "=r"(r3) : "r"(addr));
}
__device__ __forceinline__ void mma_f16(float c[4], uint32_t a0, uint32_t a1, uint32_t a2,
                                        uint32_t a3, uint32_t b0, uint32_t b1) {
    asm volatile("mma.sync.aligned.m16n8k16.row.col.f32.f16.f16.f32 "
                 "{%0,%1,%2,%3}, {%4,%5,%6,%7}, {%8,%9}, {%0,%1,%2,%3};"
                 : "+f"(c[0]), "+f"(c[1]), "+f"(c[2]), "+f"(c[3])
                 : "r"(a0), "r"(a1), "r"(a2), "r"(a3), "r"(b0), "r"(b1));
}
#define MBARRIER_INIT(addr, cnt) \
    asm volatile("mbarrier.init.shared.b64 [%0], %1;" :: "r"((uint32_t)(addr)), "r"((uint32_t)(cnt)) : "memory")
#define MBARRIER_ARRIVE(addr) \
    asm volatile("mbarrier.arrive.shared.b64 _, [%0];" :: "r"((uint32_t)(addr)) : "memory")
#define MBARRIER_WAIT_PARITY(addr, par) do {                                        \
    uint32_t _m = (uint32_t)(addr); uint32_t _p = (uint32_t)(par); uint32_t _d;     \
    asm volatile("{\n\t.reg .pred p;\n\t"                                           \
        "mbarrier.try_wait.parity.shared.b64 p, [%1], %2;\n\t"                      \
        "selp.b32 %0, 1, 0, p;\n\t}" : "=r"(_d) : "r"(_m), "r"(_p) : "memory");     \
    if (!_d) {                                                                      \
        asm volatile("{\n\t.reg .pred P1;\n\t"                                      \
        "WL_%=:\n\t"                                                                \
        "mbarrier.try_wait.parity.shared.b64 P1, [%0], %1;\n\t"                     \
        "@P1 bra.uni WD_%=;\n\tbra.uni WL_%=;\n\tWD_%=:\n\t}"                       \
        :: "r"(_m), "r"(_p) : "memory");                                            \
    }                                                                               \
} while (0)

// ---------------- prologue: x -> xT[b][p][cin] fp16 ----------------
__global__ void xt_kernel(const float* __restrict__ x) {
    int t = blockIdx.x * blockDim.x + threadIdx.x;
    if (t >= B_ * HW_) return;
    int b = t / HW_;
    int p = t % HW_;
    const float* src = x + (size_t)b * CIN_ * HW_ + p;
    uint32_t row[32];
    #pragma unroll
    for (int c = 0; c < 32; c++)
        row[c] = pack_h2(src[(2 * c) * HW_], src[(2 * c + 1) * HW_]);
    uint4* dst = (uint4*)(g_xT + (size_t)t * CIN_);
    #pragma unroll
    for (int q = 0; q < 8; q++)
        dst[q] = make_uint4(row[q * 4], row[q * 4 + 1], row[q * 4 + 2], row[q * 4 + 3]);
}

// ---------------- prologue: tap tables ----------------
__global__ void tap_kernel(const float* __restrict__ flow) {
    int t = blockIdx.x * blockDim.x + threadIdx.x;
    if (t >= NF_ * HW_) return;
    int nf = t / HW_;
    int p  = t % HW_;
    int i  = p / W_;
    int j  = p % W_;

    float fx = flow[((nf * H_ + i) * W_ + j) * 2 + 0];
    float fy = flow[((nf * H_ + i) * W_ + j) * 2 + 1];
    float ix = (float)i + fx;
    float iy = (float)j + fy;
    float bxf = floorf(ix), byf = floorf(iy);
    float s = ix - bxf, tt = iy - byf;
    int bx = (int)bxf, by = (int)byf;

    // NOTE: w10 intentionally equals w01 (replicates the reference's bug).
    float w00 = (1.f - s) * (1.f - tt);
    float w01 = s * (1.f - tt);
    float w10 = s * (1.f - tt);
    float w11 = s * tt;

    int   rs[4] = {bx, bx + 1, bx, bx + 1};
    int   cs[4] = {by, by, by + 1, by + 1};
    float ws[4] = {w00, w01, w10, w11};

    uint32_t o[4], wh[4];
    #pragma unroll
    for (int k = 0; k < 4; k++) {
        int r = min(max(rs[k], 0), H_);
        int c = min(max(cs[k], 0), W_);
        float w = (r == H_ || c == W_) ? 0.f : ws[k];       // zero-pad tap
        int idx = (r == H_ || c == W_) ? 0 : (r * W_ + c);
        o[k]  = (uint32_t)(idx * 128);
        wh[k] = pack_h2(w, w);                              // duplicated half2
    }
    g_tapO4[nf * HW_ + p] = make_uint4(o[0], o[1], o[2], o[3]);
    g_tapWh[nf * HW_ + p] = make_uint4(wh[0], wh[1], wh[2], wh[3]);
}

// ---------------- prologue: comb -> B mma fragments (k = nf*64 + cin) --------
// Index: ((kc*4 + ks)*16 + jn_g)*32 + lane ; words (x,y,z,w) =
//   x: b_lo for n-slice nb..nb+8, y: b_lo for nb+8..+16, z/w: b_hi (k+=8)
__global__ void comb_prep(const float* __restrict__ comb) {
    int t = blockIdx.x * blockDim.x + threadIdx.x;
    if (t >= NCHUNK * 4 * 16 * 32) return;
    int lane = t & 31;
    int jn_g = (t >> 5) & 15;
    int ks   = (t >> 9) & 3;
    int kc   = t >> 11;                  // = nf
    int nb = jn_g * 16;
    int kb = ks * 16;
    int n0 = nb + (lane >> 2);
    int k0 = kb + (lane & 3) * 2;
    // original comb column for (cin=k_local, nf=kc): cin*NF + nf
    auto F = [&](int n, int kl) -> float { return comb[(size_t)n * K_ + kl * NF_ + kc]; };
    uint4 u;
    u.x = pack_h2(F(n0,     k0),     F(n0,     k0 + 1));
    u.y = pack_h2(F(n0 + 8, k0),     F(n0 + 8, k0 + 1));
    u.z = pack_h2(F(n0,     k0 + 8), F(n0,     k0 + 9));
    u.w = pack_h2(F(n0 + 8, k0 + 8), F(n0 + 8, k0 + 9));
    g_combF[t] = u;
}

// ---------------- fused warp-specialized kernel ----------------
__global__ __launch_bounds__(NTHREADS, 1)
void mma_kernel(const float* __restrict__ bias, float* __restrict__ out) {
    extern __shared__ char smem[];
    const uint32_t sb = smem_u32(smem);
    const int tx   = threadIdx.x;
    const int wid  = tx >> 5;
    const int lane = tx & 31;
    const int m0   = blockIdx.x * MT;

    if (tx == 0) {
        #pragma unroll
        for (int s = 0; s < NSTAGE; s++) {
            MBARRIER_INIT(sb + s * 8, 256);       // full:  256 producer threads
            MBARRIER_INIT(sb + 32 + s * 8, 256);  // empty: 256 consumer threads
        }
    }
    __syncthreads();

    if (wid >= 8) {
        // ================= PRODUCER (warps 8-15): A only =================
        const int pt = tx - 256;          // 0..255
        const int L  = pt & 15;           // 8-byte cin group
        const int rb = pt >> 4;           // row base 0..15 (rows rb + 16*j)

        const char* xrow[4];
        int         pp[4];
        uint32_t    sAoff[4];
        #pragma unroll
        for (int j = 0; j < 4; j++) {
            int ml = rb + 16 * j;
            int m  = m0 + ml;
            int b  = m / HW_;
            int p  = m - b * HW_;
            xrow[j]  = (const char*)g_xT + (size_t)b * (HW_ * CIN_ * 2) + L * 8;
            pp[j]    = p;
            sAoff[j] = (uint32_t)(ml * 128) + (((uint32_t)(L * 8)) ^ ((uint32_t)(ml & 7) << 4));
        }

        #pragma unroll 1
        for (int kc = 0; kc < NCHUNK; kc++) {
            const int s = kc & 3;
            if (kc >= NSTAGE)
                MBARRIER_WAIT_PARITY(sb + 32 + s * 8, ((kc - NSTAGE) >> 2) & 1);

            // ---- A: coalesced gathers, HFMA2 tap math ----
            char* aB = smem + OFF_A + s * 8192;
            const uint4* tO = g_tapO4 + kc * HW_;
            const uint4* tW = g_tapWh + kc * HW_;
            #pragma unroll
            for (int j = 0; j < 4; j++) {
                uint4 o4 = __ldg(tO + pp[j]);
                uint4 w4 = __ldg(tW + pp[j]);
                const char* xb = xrow[j];
                uint2 d0 = *(const uint2*)(xb + o4.x);
                uint2 d1 = *(const uint2*)(xb + o4.y);
                uint2 d2 = *(const uint2*)(xb + o4.z);
                uint2 d3 = *(const uint2*)(xb + o4.w);
                __half2 w0 = *(const __half2*)&w4.x;
                __half2 w1 = *(const __half2*)&w4.y;
                __half2 w2 = *(const __half2*)&w4.z;
                __half2 w3 = *(const __half2*)&w4.w;
                __half2 lo = __hmul2(*(const __half2*)&d0.x, w0);
                lo = __hfma2(*(const __half2*)&d1.x, w1, lo);
                lo = __hfma2(*(const __half2*)&d2.x, w2, lo);
                lo = __hfma2(*(const __half2*)&d3.x, w3, lo);
                __half2 hi = __hmul2(*(const __half2*)&d0.y, w0);
                hi = __hfma2(*(const __half2*)&d1.y, w1, hi);
                hi = __hfma2(*(const __half2*)&d2.y, w2, hi);
                hi = __hfma2(*(const __half2*)&d3.y, w3, hi);
                *(uint2*)(aB + sAoff[j]) =
                    make_uint2(*(const uint32_t*)&lo, *(const uint32_t*)&hi);
            }
            MBARRIER_ARRIVE(sb + s * 8);
        }
    } else {
        // ================= CONSUMER (warps 0-7) =================
        const int warpM = wid & 1;        // M half: rows [warpM*32, +32)
        const int warpN = wid >> 1;       // N slice [warpN*64, +64)
        float acc[2][8][4];
        #pragma unroll
        for (int i = 0; i < 2; i++)
            #pragma unroll
            for (int j = 0; j < 8; j++)
                #pragma unroll
                for (int q = 0; q < 4; q++) acc[i][j][q] = 0.f;

        auto lm_addr = [&](uint32_t base, int rowBase, int kByte) -> uint32_t {
            int r  = rowBase + (lane & 7) + 8 * ((lane >> 3) & 1);
            int cb = kByte + 16 * (lane >> 4);
            return base + r * 128 + (uint32_t)(cb ^ ((r & 7) << 4));
        };

        #pragma unroll 1
        for (int kc = 0; kc < NCHUNK; kc++) {
            const int s = kc & 3;
            // B fragments for this chunk, software-pipelined per k-step.
            const uint4* cb = g_combF + ((size_t)kc * 64 + warpN * 4) * 32 + lane;

            uint4 bf[2][4];
            #pragma unroll
            for (int jn = 0; jn < 4; jn++)
                bf[0][jn] = __ldg(cb + jn * 32);          // ks=0, before A-wait

            MBARRIER_WAIT_PARITY(sb + s * 8, (kc >> 2) & 1);
            const uint32_t aBuf = sb + OFF_A + s * 8192;

            #pragma unroll
            for (int ks = 0; ks < 4; ks++) {
                if (ks < 3) {
                    #pragma unroll
                    for (int jn = 0; jn < 4; jn++)
                        bf[(ks + 1) & 1][jn] = __ldg(cb + ((ks + 1) * 16 + jn) * 32);
                }
                const int kB = ks * 32;
                uint32_t a0, a1, a2, a3, c0, c1, c2, c3;
                ldsm_x4(a0, a1, a2, a3, lm_addr(aBuf, warpM * 32 + 0, kB));
                ldsm_x4(c0, c1, c2, c3, lm_addr(aBuf, warpM * 32 + 16, kB));
                const uint4* bb = bf[ks & 1];
                #pragma unroll
                for (int jn = 0; jn < 4; jn++) {
                    mma_f16(acc[0][jn * 2 + 0], a0, a1, a2, a3, bb[jn].x, bb[jn].z);
                    mma_f16(acc[0][jn * 2 + 1], a0, a1, a2, a3, bb[jn].y, bb[jn].w);
                    mma_f16(acc[1][jn * 2 + 0], c0, c1, c2, c3, bb[jn].x, bb[jn].z);
                    mma_f16(acc[1][jn * 2 + 1], c0, c1, c2, c3, bb[jn].y, bb[jn].w);
                }
            }
            MBARRIER_ARRIVE(sb + 32 + s * 8);
        }

        // ---- epilogue ----
        const int r = lane >> 2;
        const int c = lane & 3;
        #pragma unroll
        for (int wm = 0; wm < 2; wm++) {
            int mr0 = m0 + warpM * 32 + wm * 16 + r;
            int mr1 = mr0 + 8;
            int b0i = mr0 / HW_, p0 = mr0 - b0i * HW_;
            int b1i = mr1 / HW_, p1 = mr1 - b1i * HW_;
            float* o0 = out + (size_t)b0i * COUT_ * HW_ + p0;
            float* o1 = out + (size_t)b1i * COUT_ * HW_ + p1;
            #pragma unroll
            for (int j = 0; j < 8; j++) {
                int n0 = warpN * 64 + (j >> 1) * 16 + (j & 1) * 8 + 2 * c;
                float bz0 = __ldg(bias + n0), bz1 = __ldg(bias + n0 + 1);
                o0[(size_t)n0 * HW_]       = acc[wm][j][0] + bz0;
                o0[(size_t)(n0 + 1) * HW_] = acc[wm][j][1] + bz1;
                o1[(size_t)n0 * HW_]       = acc[wm][j][2] + bz0;
                o1[(size_t)(n0 + 1) * HW_] = acc[wm][j][3] + bz1;
            }
        }
    }
}

extern "C" void kernel_launch(void* const* d_in, const int* in_sizes, int n_in,
                              void* d_out, int out_size) {
    const float* x    = (const float*)d_in[0];
    const float* flow = (const float*)d_in[1];
    const float* comb = (const float*)d_in[2];
    const float* bias = (const float*)d_in[3];
    float* out = (float*)d_out;

    cudaFuncSetAttribute(mma_kernel,
                         cudaFuncAttributeMaxDynamicSharedMemorySize, SMEM_TOTAL);

    xt_kernel<<<(B_ * HW_ + 127) / 128, 128>>>(x);
    tap_kernel<<<(NF_ * HW_ + 255) / 256, 256>>>(flow);
    comb_prep<<<(NCHUNK * 4 * 16 * 32 + 255) / 256, 256>>>(comb);
    mma_kernel<<<M_ / MT, NTHREADS, SMEM_TOTAL>>>(bias, out);
}

// round 16
// speedup vs baseline: 1.2969x; 1.0520x over previous
#include <cuda_runtime.h>
#include <cuda_fp16.h>
#include <cstdint>

// ---------------- problem constants ----------------
#define B_    128
#define CIN_  64
#define NF_   16
#define COUT_ 256
#define H_    20
#define W_    20
#define HW_   400
#define K_    1024
#define M_    51200

#define MT      32       // M rows per CTA tile (2 CTAs per SM)
#define KC      64       // K per chunk = 64 cin of one nf  (chunk kc <-> nf)
#define NCHUNK  16
#define NSTAGE  4
#define NTHREADS 256     // 4 consumer + 4 producer warps

// ---------------- smem layout (bytes) ----------------
// mbar  [0, 64)    full[s]=s*8, empty[s]=32+s*8
// A     [1024, 17408)   4 x (32 rows x 128B) fp16
#define OFF_A    1024
#define SMEM_TOTAL 17408

// ---------------- device scratch ----------------
__device__ __half g_xT[B_ * HW_ * CIN_];          // 6.55MB: [b][p][cin] fp16
__device__ uint4  g_combF[NCHUNK * 4 * 16 * 32];  // 512KB: B mma fragments
__device__ uint4  g_tapO4[NF_ * HW_];             // 4 byte-offsets (rows) into xT slab
__device__ uint4  g_tapWh[NF_ * HW_];             // 4 weights as duplicated half2

// ---------------- helpers ----------------
__device__ __forceinline__ uint32_t smem_u32(const void* p) {
    uint32_t a;
    asm("{ .reg .u64 t; cvta.to.shared.u64 t, %1; cvt.u32.u64 %0, t; }" : "=r"(a) : "l"(p));
    return a;
}
__device__ __forceinline__ uint32_t pack_h2(float lo, float hi) {
    uint32_t u;
    asm("cvt.rn.f16x2.f32 %0, %1, %2;" : "=r"(u) : "f"(hi), "f"(lo));
    return u;
}
__device__ __forceinline__ void ldsm_x4(uint32_t& r0, uint32_t& r1, uint32_t& r2, uint32_t& r3,
                                        uint32_t addr) {
    asm volatile("ldmatrix.sync.aligned.m8n8.x4.shared.b16 {%0,%1,%2,%3}, [%4];"
                 : "=r"(r0), "=r"(r1), "=r"(r2), "=r"(r3) : "r"(addr));
}
__device__ __forceinline__ void mma_f16(float c[4], uint32_t a0, uint32_t a1, uint32_t a2,
                                        uint32_t a3, uint32_t b0, uint32_t b1) {
    asm volatile("mma.sync.aligned.m16n8k16.row.col.f32.f16.f16.f32 "
                 "{%0,%1,%2,%3}, {%4,%5,%6,%7}, {%8,%9}, {%0,%1,%2,%3};"
                 : "+f"(c[0]), "+f"(c[1]), "+f"(c[2]), "+f"(c[3])
                 : "r"(a0), "r"(a1), "r"(a2), "r"(a3), "r"(b0), "r"(b1));
}
#define MBARRIER_INIT(addr, cnt) \
    asm volatile("mbarrier.init.shared.b64 [%0], %1;" :: "r"((uint32_t)(addr)), "r"((uint32_t)(cnt)) : "memory")
#define MBARRIER_ARRIVE(addr) \
    asm volatile("mbarrier.arrive.shared.b64 _, [%0];" :: "r"((uint32_t)(addr)) : "memory")
#define MBARRIER_WAIT_PARITY(addr, par) do {                                        \
    uint32_t _m = (uint32_t)(addr); uint32_t _p = (uint32_t)(par); uint32_t _d;     \
    asm volatile("{\n\t.reg .pred p;\n\t"                                           \
        "mbarrier.try_wait.parity.shared.b64 p, [%1], %2;\n\t"                      \
        "selp.b32 %0, 1, 0, p;\n\t}" : "=r"(_d) : "r"(_m), "r"(_p) : "memory");     \
    if (!_d) {                                                                      \
        asm volatile("{\n\t.reg .pred P1;\n\t"                                      \
        "WL_%=:\n\t"                                                                \
        "mbarrier.try_wait.parity.shared.b64 P1, [%0], %1;\n\t"                     \
        "@P1 bra.uni WD_%=;\n\tbra.uni WL_%=;\n\tWD_%=:\n\t}"                       \
        :: "r"(_m), "r"(_p) : "memory");                                            \
    }                                                                               \
} while (0)

// ---------------- prologue: x -> xT[b][p][cin] fp16 ----------------
__global__ void xt_kernel(const float* __restrict__ x) {
    int t = blockIdx.x * blockDim.x + threadIdx.x;
    if (t >= B_ * HW_) return;
    int b = t / HW_;
    int p = t % HW_;
    const float* src = x + (size_t)b * CIN_ * HW_ + p;
    uint32_t row[32];
    #pragma unroll
    for (int c = 0; c < 32; c++)
        row[c] = pack_h2(src[(2 * c) * HW_], src[(2 * c + 1) * HW_]);
    uint4* dst = (uint4*)(g_xT + (size_t)t * CIN_);
    #pragma unroll
    for (int q = 0; q < 8; q++)
        dst[q] = make_uint4(row[q * 4], row[q * 4 + 1], row[q * 4 + 2], row[q * 4 + 3]);
}

// ---------------- prologue: tap tables ----------------
__global__ void tap_kernel(const float* __restrict__ flow) {
    int t = blockIdx.x * blockDim.x + threadIdx.x;
    if (t >= NF_ * HW_) return;
    int nf = t / HW_;
    int p  = t % HW_;
    int i  = p / W_;
    int j  = p % W_;

    float fx = flow[((nf * H_ + i) * W_ + j) * 2 + 0];
    float fy = flow[((nf * H_ + i) * W_ + j) * 2 + 1];
    float ix = (float)i + fx;
    float iy = (float)j + fy;
    float bxf = floorf(ix), byf = floorf(iy);
    float s = ix - bxf, tt = iy - byf;
    int bx = (int)bxf, by = (int)byf;

    // NOTE: w10 intentionally equals w01 (replicates the reference's bug).
    float w00 = (1.f - s) * (1.f - tt);
    float w01 = s * (1.f - tt);
    float w10 = s * (1.f - tt);
    float w11 = s * tt;

    int   rs[4] = {bx, bx + 1, bx, bx + 1};
    int   cs[4] = {by, by, by + 1, by + 1};
    float ws[4] = {w00, w01, w10, w11};

    uint32_t o[4], wh[4];
    #pragma unroll
    for (int k = 0; k < 4; k++) {
        int r = min(max(rs[k], 0), H_);
        int c = min(max(cs[k], 0), W_);
        float w = (r == H_ || c == W_) ? 0.f : ws[k];       // zero-pad tap
        int idx = (r == H_ || c == W_) ? 0 : (r * W_ + c);
        o[k]  = (uint32_t)(idx * 128);
        wh[k] = pack_h2(w, w);                              // duplicated half2
    }
    g_tapO4[nf * HW_ + p] = make_uint4(o[0], o[1], o[2], o[3]);
    g_tapWh[nf * HW_ + p] = make_uint4(wh[0], wh[1], wh[2], wh[3]);
}

// ---------------- prologue: comb -> B mma fragments (k = nf*64 + cin) --------
// Index: ((kc*4 + ks)*16 + jn_g)*32 + lane ; words (x,y,z,w) =
//   x: b_lo for n-slice nb..nb+8, y: b_lo for nb+8..+16, z/w: b_hi (k+=8)
__global__ void comb_prep(const float* __restrict__ comb) {
    int t = blockIdx.x * blockDim.x + threadIdx.x;
    if (t >= NCHUNK * 4 * 16 * 32) return;
    int lane = t & 31;
    int jn_g = (t >> 5) & 15;
    int ks   = (t >> 9) & 3;
    int kc   = t >> 11;                  // = nf
    int nb = jn_g * 16;
    int kb = ks * 16;
    int n0 = nb + (lane >> 2);
    int k0 = kb + (lane & 3) * 2;
    // original comb column for (cin=k_local, nf=kc): cin*NF + nf
    auto F = [&](int n, int kl) -> float { return comb[(size_t)n * K_ + kl * NF_ + kc]; };
    uint4 u;
    u.x = pack_h2(F(n0,     k0),     F(n0,     k0 + 1));
    u.y = pack_h2(F(n0 + 8, k0),     F(n0 + 8, k0 + 1));
    u.z = pack_h2(F(n0,     k0 + 8), F(n0,     k0 + 9));
    u.w = pack_h2(F(n0 + 8, k0 + 8), F(n0 + 8, k0 + 9));
    g_combF[t] = u;
}

// ---------------- fused warp-specialized kernel (2 CTAs / SM) ----------------
__global__ __launch_bounds__(NTHREADS, 2)
void mma_kernel(const float* __restrict__ bias, float* __restrict__ out) {
    extern __shared__ char smem[];
    const uint32_t sb = smem_u32(smem);
    const int tx   = threadIdx.x;
    const int wid  = tx >> 5;
    const int lane = tx & 31;
    const int m0   = blockIdx.x * MT;

    if (tx == 0) {
        #pragma unroll
        for (int s = 0; s < NSTAGE; s++) {
            MBARRIER_INIT(sb + s * 8, 128);       // full:  128 producer threads
            MBARRIER_INIT(sb + 32 + s * 8, 128);  // empty: 128 consumer threads
        }
    }
    __syncthreads();

    if (wid >= 4) {
        // ================= PRODUCER (warps 4-7): A only =================
        const int pt = tx - 128;          // 0..127
        const int L  = pt & 15;           // 8-byte cin group
        const int rb = pt >> 4;           // row base 0..7 (rows rb + 8*j)

        const char* xrow[4];
        int         pp[4];
        uint32_t    sAoff[4];
        #pragma unroll
        for (int j = 0; j < 4; j++) {
            int ml = rb + 8 * j;
            int m  = m0 + ml;
            int b  = m / HW_;
            int p  = m - b * HW_;
            xrow[j]  = (const char*)g_xT + (size_t)b * (HW_ * CIN_ * 2) + L * 8;
            pp[j]    = p;
            sAoff[j] = (uint32_t)(ml * 128) + (((uint32_t)(L * 8)) ^ ((uint32_t)(ml & 7) << 4));
        }

        #pragma unroll 1
        for (int kc = 0; kc < NCHUNK; kc++) {
            const int s = kc & 3;
            if (kc >= NSTAGE)
                MBARRIER_WAIT_PARITY(sb + 32 + s * 8, ((kc - NSTAGE) >> 2) & 1);

            // ---- A: coalesced gathers, HFMA2 tap math ----
            char* aB = smem + OFF_A + s * 4096;
            const uint4* tO = g_tapO4 + kc * HW_;
            const uint4* tW = g_tapWh + kc * HW_;
            #pragma unroll
            for (int j = 0; j < 4; j++) {
                uint4 o4 = __ldg(tO + pp[j]);
                uint4 w4 = __ldg(tW + pp[j]);
                const char* xb = xrow[j];
                uint2 d0 = *(const uint2*)(xb + o4.x);
                uint2 d1 = *(const uint2*)(xb + o4.y);
                uint2 d2 = *(const uint2*)(xb + o4.z);
                uint2 d3 = *(const uint2*)(xb + o4.w);
                __half2 w0 = *(const __half2*)&w4.x;
                __half2 w1 = *(const __half2*)&w4.y;
                __half2 w2 = *(const __half2*)&w4.z;
                __half2 w3 = *(const __half2*)&w4.w;
                __half2 lo = __hmul2(*(const __half2*)&d0.x, w0);
                lo = __hfma2(*(const __half2*)&d1.x, w1, lo);
                lo = __hfma2(*(const __half2*)&d2.x, w2, lo);
                lo = __hfma2(*(const __half2*)&d3.x, w3, lo);
                __half2 hi = __hmul2(*(const __half2*)&d0.y, w0);
                hi = __hfma2(*(const __half2*)&d1.y, w1, hi);
                hi = __hfma2(*(const __half2*)&d2.y, w2, hi);
                hi = __hfma2(*(const __half2*)&d3.y, w3, hi);
                *(uint2*)(aB + sAoff[j]) =
                    make_uint2(*(const uint32_t*)&lo, *(const uint32_t*)&hi);
            }
            MBARRIER_ARRIVE(sb + s * 8);
        }
    } else {
        // ================= CONSUMER (warps 0-3) =================
        const int warpN = wid;            // N slice [warpN*64, +64), full M=32
        float acc[2][8][4];
        #pragma unroll
        for (int i = 0; i < 2; i++)
            #pragma unroll
            for (int j = 0; j < 8; j++)
                #pragma unroll
                for (int q = 0; q < 4; q++) acc[i][j][q] = 0.f;

        auto lm_addr = [&](uint32_t base, int rowBase, int kByte) -> uint32_t {
            int r  = rowBase + (lane & 7) + 8 * ((lane >> 3) & 1);
            int cb = kByte + 16 * (lane >> 4);
            return base + r * 128 + (uint32_t)(cb ^ ((r & 7) << 4));
        };

        #pragma unroll 1
        for (int kc = 0; kc < NCHUNK; kc++) {
            const int s = kc & 3;
            // B fragments for this chunk, software-pipelined per k-step.
            const uint4* cb = g_combF + ((size_t)kc * 64 + warpN * 4) * 32 + lane;

            uint4 bf[2][4];
            #pragma unroll
            for (int jn = 0; jn < 4; jn++)
                bf[0][jn] = __ldg(cb + jn * 32);          // ks=0, before A-wait

            MBARRIER_WAIT_PARITY(sb + s * 8, (kc >> 2) & 1);
            const uint32_t aBuf = sb + OFF_A + s * 4096;

            #pragma unroll
            for (int ks = 0; ks < 4; ks++) {
                if (ks < 3) {
                    #pragma unroll
                    for (int jn = 0; jn < 4; jn++)
                        bf[(ks + 1) & 1][jn] = __ldg(cb + ((ks + 1) * 16 + jn) * 32);
                }
                const int kB = ks * 32;
                uint32_t a0, a1, a2, a3, c0, c1, c2, c3;
                ldsm_x4(a0, a1, a2, a3, lm_addr(aBuf, 0, kB));
                ldsm_x4(c0, c1, c2, c3, lm_addr(aBuf, 16, kB));
                const uint4* bb = bf[ks & 1];
                #pragma unroll
                for (int jn = 0; jn < 4; jn++) {
                    mma_f16(acc[0][jn * 2 + 0], a0, a1, a2, a3, bb[jn].x, bb[jn].z);
                    mma_f16(acc[0][jn * 2 + 1], a0, a1, a2, a3, bb[jn].y, bb[jn].w);
                    mma_f16(acc[1][jn * 2 + 0], c0, c1, c2, c3, bb[jn].x, bb[jn].z);
                    mma_f16(acc[1][jn * 2 + 1], c0, c1, c2, c3, bb[jn].y, bb[jn].w);
                }
            }
            MBARRIER_ARRIVE(sb + 32 + s * 8);
        }

        // ---- epilogue ----
        const int r = lane >> 2;
        const int c = lane & 3;
        #pragma unroll
        for (int wm = 0; wm < 2; wm++) {
            int mr0 = m0 + wm * 16 + r;
            int mr1 = mr0 + 8;
            int b0i = mr0 / HW_, p0 = mr0 - b0i * HW_;
            int b1i = mr1 / HW_, p1 = mr1 - b1i * HW_;
            float* o0 = out + (size_t)b0i * COUT_ * HW_ + p0;
            float* o1 = out + (size_t)b1i * COUT_ * HW_ + p1;
            #pragma unroll
            for (int j = 0; j < 8; j++) {
                int n0 = warpN * 64 + (j >> 1) * 16 + (j & 1) * 8 + 2 * c;
                float bz0 = __ldg(bias + n0), bz1 = __ldg(bias + n0 + 1);
                o0[(size_t)n0 * HW_]       = acc[wm][j][0] + bz0;
                o0[(size_t)(n0 + 1) * HW_] = acc[wm][j][1] + bz1;
                o1[(size_t)n0 * HW_]       = acc[wm][j][2] + bz0;
                o1[(size_t)(n0 + 1) * HW_] = acc[wm][j][3] + bz1;
            }
        }
    }
}

extern "C" void kernel_launch(void* const* d_in, const int* in_sizes, int n_in,
                              void* d_out, int out_size) {
    const float* x    = (const float*)d_in[0];
    const float* flow = (const float*)d_in[1];
    const float* comb = (const float*)d_in[2];
    const float* bias = (const float*)d_in[3];
    float* out = (float*)d_out;

    cudaFuncSetAttribute(mma_kernel,
                         cudaFuncAttributeMaxDynamicSharedMemorySize, SMEM_TOTAL);

    xt_kernel<<<(B_ * HW_ + 127) / 128, 128>>>(x);
    tap_kernel<<<(NF_ * HW_ + 255) / 256, 256>>>(flow);
    comb_prep<<<(NCHUNK * 4 * 16 * 32 + 255) / 256, 256>>>(comb);
    mma_kernel<<<M_ / MT, NTHREADS, SMEM_TOTAL>>>(bias, out);
}